// round 13
// baseline (speedup 1.0000x reference)
#include <cuda_runtime.h>
#include <stdint.h>

// Problem constants (match reference)
#define N_ELEMS   4194304        // total elements
#define N4        (N_ELEMS / 4)  // feats as float4
#define NUM_IDS   262144
#define M_CAP     (NUM_IDS + 1)  // 262145 output rows
#define L_CAP     128
#define OUT_TOTAL (M_CAP + M_CAP * L_CAP)   // 33,816,705 floats
#define NW        264193         // full 128-float windows (NW*128 = OUT_TOTAL-1)
#define WPW       8              // windows per warp
#define NWG       33025          // warp-groups = ceil(NW / WPW)

// Scan decomposition: 512 blocks * 8192 elems; 256 threads * 32 items/thread
// (8 front-batched LDG.128 per thread -> MLP ~8; bitmask body keeps regs low)
#define NB        512
#define EPB       8192
#define BLK       256
#define IPT       32

// Scratch (device globals: no allocation allowed)
__device__ __align__(16) int   g_start[M_CAP];     // start index of run s
__device__ __align__(16) float g_idf[M_CAP];       // float(id) for written runs
__device__ __align__(16) int   g_sstart[NB * EPB]; // per-block stash: starts
__device__ __align__(16) float g_sidf[NB * EPB];   // per-block stash: float(id)
__device__ int g_block_cnt[NB];                    // runs per block
__device__ int g_num_runs;

// ---------------------------------------------------------------------------
// Kernel A: single ids read (8x LDG.128/thread front-batched); boundary
// BITMASK (popc count, ffs scatter — avg ~2 set bits per thread); block-local
// rank scan; stash runs into the block's private segment. NO cross-block
// communication. Each thread's 32 ids = exactly one 128B line -> the scatter
// reload ids[i0+j] is an L1 hit and avoids keeping v[] live (reg pressure).
// ---------------------------------------------------------------------------
__global__ __launch_bounds__(BLK, 6) void k_count_stash(const int* __restrict__ ids) {
    const int b  = blockIdx.x;
    const int t  = threadIdx.x;
    const int i0 = b * EPB + t * IPT;

    // 8 independent vector loads, front-batched
    const int4* p = reinterpret_cast<const int4*>(ids + i0);
    int4 a[IPT / 4];
#pragma unroll
    for (int j = 0; j < IPT / 4; j++) a[j] = p[j];

    const int first_prev = (i0 == 0) ? ~a[0].x : ids[i0 - 1];

    // boundary bitmask (consume a[] in order; no persistent v[] array)
    unsigned bm = 0;
    int prev = first_prev;
#pragma unroll
    for (int j = 0; j < IPT / 4; j++) {
        bm |= (unsigned)(a[j].x != prev) << (4 * j + 0);
        bm |= (unsigned)(a[j].y != a[j].x) << (4 * j + 1);
        bm |= (unsigned)(a[j].z != a[j].y) << (4 * j + 2);
        bm |= (unsigned)(a[j].w != a[j].z) << (4 * j + 3);
        prev = a[j].w;
    }
    const int cnt = __popc(bm);

    // block-wide exclusive scan of per-thread counts (2-level shuffle)
    const int lane = t & 31;
    const int wid  = t >> 5;
    int s = cnt;
#pragma unroll
    for (int off = 1; off < 32; off <<= 1) {
        int x = __shfl_up_sync(0xFFFFFFFFu, s, off);
        if (lane >= off) s += x;
    }
    __shared__ int ws[BLK / 32];
    if (lane == 31) ws[wid] = s;
    __syncthreads();
    if (wid == 0 && lane < BLK / 32) {
        int x = ws[lane];
        int y = x;
#pragma unroll
        for (int off = 1; off < BLK / 32; off <<= 1) {
            int z = __shfl_up_sync(0xFFu, y, off);
            if (lane >= off) y += z;
        }
        ws[lane] = y - x;                        // exclusive warp base
        if (lane == BLK / 32 - 1) g_block_cnt[b] = y;   // block total
    }
    __syncthreads();
    int r = ws[wid] + (s - cnt);                 // local rank within block

    // scatter ONLY set bits; value reloaded via ids[] (L1-resident line)
    const int seg = b * EPB;
    while (bm) {
        const int j = __ffs(bm) - 1;
        bm &= bm - 1;
        g_sstart[seg + r] = i0 + j;
        g_sidf[seg + r]   = (float)ids[i0 + j];
        r++;
    }
}

// ---------------------------------------------------------------------------
// Kernel C: block b computes base = sum(g_block_cnt[0..b-1]) directly (all
// counts final — previous kernel ended; <=2 hot-L2 loads per thread), then
// copies its stash segment to the final rank-indexed arrays.
// ---------------------------------------------------------------------------
__global__ __launch_bounds__(BLK) void k_apply() {
    const int b = blockIdx.x;
    const int t = threadIdx.x;
    const int lane = t & 31;
    const int wid  = t >> 5;

    int part = 0;
    for (int j = t; j < b; j += BLK)             // <= 2 iterations
        part += g_block_cnt[j];
#pragma unroll
    for (int off = 16; off > 0; off >>= 1)
        part += __shfl_down_sync(0xFFFFFFFFu, part, off);
    __shared__ int rs[BLK / 32];
    __shared__ int sBase;
    if (lane == 0) rs[wid] = part;
    __syncthreads();
    if (t == 0) {
        int acc = 0;
#pragma unroll
        for (int k = 0; k < BLK / 32; k++) acc += rs[k];
        sBase = acc;
    }
    __syncthreads();
    const int base = sBase;
    const int cnt  = g_block_cnt[b];

    if (b == NB - 1 && t == 0) g_num_runs = base + cnt;

    const int seg = b * EPB;
    for (int j = t; j < cnt; j += BLK) {
        g_start[base + j] = g_sstart[seg + j];
        g_idf[base + j]   = g_sidf[seg + j];
    }
}

// ---------------------------------------------------------------------------
// Kernel 2: one WARP per EIGHT consecutive 128-float output windows.
// Flat layout (float32): out[0..M_CAP) = run_ids, then padded [M_CAP x 128].
// M_CAP % 128 == 1: window w>=2048 = col 127 of row A=w-2049 then cols
// 0..126 of row B=A+1 (window 2048: A=-1, head = run_ids[M_CAP-1] == -1).
// Per-window feats span is ONE contiguous 512B block [sB-off, sB-off+128),
// off = sB & 3: one aligned LDG.128 per lane + 0-2 warp shuffles keyed by
// the warp-uniform off. Lane-0 head (col 127 of row A) is one predicated
// scalar load. (R11/R12 proven version.)
// ---------------------------------------------------------------------------
__global__ __launch_bounds__(256) void k_fill(const float* __restrict__ feats,
                                              float* __restrict__ out) {
    if (blockIdx.x == 0 && threadIdx.x == 0)
        out[OUT_TOTAL - 1] = 0.0f;                // tail float (padding)

    const int W    = blockIdx.x * 8 + (threadIdx.x >> 5);   // warp-group id
    const int lane = threadIdx.x & 31;
    if (W >= NWG) return;
    const int w0  = W * WPW;
    const int nr1 = g_num_runs - 1;               // runs actually emitted

    if (W < 256) {
        // ---- run_ids region: 8 vectorized copies with tail masking ----
#pragma unroll
        for (int k = 0; k < WPW; k++) {
            float4 r = reinterpret_cast<const float4*>(g_idf)[(w0 + k) * 32 + lane];
            const int e = (w0 + k) * 128 + lane * 4;
            r.x = (e     < nr1) ? r.x : -1.0f;
            r.y = (e + 1 < nr1) ? r.y : -1.0f;
            r.z = (e + 2 < nr1) ? r.z : -1.0f;
            r.w = (e + 3 < nr1) ? r.w : -1.0f;
            __stcs(reinterpret_cast<float4*>(out) + (size_t)(w0 + k) * 32 + lane, r);
        }
        return;
    }

    // ---- padded region ----
    const int A0 = w0 - 2049;                     // head row of window 0

    // one coalesced metadata load: g_start[A0 .. A0+9]
    int mv = 0;
    if (lane < WPW + 2) {
        int idx = A0 + lane;
        idx = idx < 0 ? 0 : idx;
        idx = idx > nr1 ? nr1 : idx;              // clamp into written region
        mv = g_start[idx];
    }
    int m[WPW + 2];
#pragma unroll
    for (int j = 0; j < WPW + 2; j++) m[j] = __shfl_sync(0xFFFFFFFFu, mv, j);

    const bool l0 = (lane == 0);
    const int  c0 = 4 * lane - 1;                 // col of element 0

#pragma unroll
    for (int h = 0; h < 2; h++) {
        float4 V[4];
        float  head[4];
        int    offk[4];
        bool   okk[4], vBk[4];
        int    lenBk[4];

        // --- batched loads for 4 windows (MLP) ---
#pragma unroll
        for (int k2 = 0; k2 < 4; k2++) {
            const int k  = h * 4 + k2;
            const int w  = w0 + k;
            okk[k2] = (w < NW);
            const int A    = A0 + k;
            const int sA   = m[k];
            const int sB   = m[k + 1];
            const int sC   = m[k + 2];
            const bool vA  = ((unsigned)A       < (unsigned)nr1);
            vBk[k2]        = ((unsigned)(A + 1) < (unsigned)nr1);
            const int lenA = sB - sA;
            lenBk[k2]      = sC - sB;
            offk[k2]       = sB & 3;

            int q = (sB >> 2) + lane;
            q = q < N4 - 1 ? q : N4 - 1;
            V[k2] = make_float4(0.f, 0.f, 0.f, 0.f);
            if (okk[k2] && vBk[k2])
                V[k2] = __ldcs(reinterpret_cast<const float4*>(feats) + q);

            head[k2] = (A < 0) ? -1.0f : 0.0f;
            if (okk[k2] && l0 && vA && lenA > 127)
                head[k2] = __ldcs(feats + sA + 127);
        }

        // --- realign + mask + store per window ---
#pragma unroll
        for (int k2 = 0; k2 < 4; k2++) {
            const int off  = offk[k2];
            const int lenB = lenBk[k2];
            const bool vB  = vBk[k2];
            float e0, e1, e2, e3;

            if (off == 1) {
                e0 = V[k2].x; e1 = V[k2].y; e2 = V[k2].z; e3 = V[k2].w;
            } else if (off == 0) {
                const float pw = __shfl_up_sync(0xFFFFFFFFu, V[k2].w, 1);
                e0 = pw;      e1 = V[k2].x; e2 = V[k2].y; e3 = V[k2].z;
            } else if (off == 2) {
                const float nx = __shfl_down_sync(0xFFFFFFFFu, V[k2].x, 1);
                e0 = V[k2].y; e1 = V[k2].z; e2 = V[k2].w; e3 = nx;
            } else {
                const float nx = __shfl_down_sync(0xFFFFFFFFu, V[k2].x, 1);
                const float ny = __shfl_down_sync(0xFFFFFFFFu, V[k2].y, 1);
                e0 = V[k2].z; e1 = V[k2].w; e2 = nx;      e3 = ny;
            }

            e0 = (vB && c0     >= 0 && c0     < lenB) ? e0 : 0.0f;
            e1 = (vB && c0 + 1 < lenB) ? e1 : 0.0f;
            e2 = (vB && c0 + 2 < lenB) ? e2 : 0.0f;
            e3 = (vB && c0 + 3 < lenB) ? e3 : 0.0f;
            if (l0) e0 = head[k2];

            if (okk[k2])
                __stcs(reinterpret_cast<float4*>(out) +
                           (size_t)(w0 + h * 4 + k2) * 32 + lane,
                       make_float4(e0, e1, e2, e3));
        }
    }
}

// ---------------------------------------------------------------------------
extern "C" void kernel_launch(void* const* d_in, const int* in_sizes, int n_in,
                              void* d_out, int out_size) {
    const int*   ids   = (const int*)d_in[0];
    const float* feats = (const float*)d_in[1];
    float*       out   = (float*)d_out;

    k_count_stash<<<NB, BLK>>>(ids);
    k_apply<<<NB, BLK>>>();

    const int fill_blocks = (NWG + 7) / 8;        // 8 warp-groups per block
    k_fill<<<fill_blocks, 256>>>(feats, out);
}

// round 14
// speedup vs baseline: 1.0548x; 1.0548x over previous
#include <cuda_runtime.h>
#include <stdint.h>

// Problem constants (match reference)
#define N_ELEMS   4194304        // total elements
#define N4        (N_ELEMS / 4)  // feats as float4
#define NUM_IDS   262144
#define M_CAP     (NUM_IDS + 1)  // 262145 output rows
#define L_CAP     128
#define OUT_TOTAL (M_CAP + M_CAP * L_CAP)   // 33,816,705 floats
#define NW        264193         // full 128-float windows (NW*128 = OUT_TOTAL-1)
#define WPW       8              // windows per warp
#define NWG       33025          // warp-groups = ceil(NW / WPW)

// Scan decomposition: 1024 blocks * 4096 elems; 256 threads * 16 items/thread
// (R12 proven: grid must stay >= 1024 blocks for residency; IPT=16)
#define NB        1024
#define EPB       4096
#define BLK       256
#define IPT       16

// Scratch (device globals: no allocation allowed)
__device__ __align__(16) int   g_start[M_CAP];     // start index of run s
__device__ __align__(16) float g_idf[M_CAP];       // float(id) for written runs
__device__ __align__(16) int2  g_stash[NB * EPB];  // per-block stash {start, id}
__device__ int g_block_cnt[NB];                    // runs per block
__device__ int g_num_runs;

// ---------------------------------------------------------------------------
// Kernel A: single ids read (4x LDG.128/thread); predecessor via shuffle/smem
// (no per-thread scalar global load); boundary BITMASK (popc count, ffs
// scatter, ONE STG.64 per run); block-local rank scan; stash runs into the
// block's private segment. NO cross-block communication.
// ---------------------------------------------------------------------------
__global__ __launch_bounds__(BLK, 8) void k_count_stash(const int* __restrict__ ids) {
    const int b  = blockIdx.x;
    const int t  = threadIdx.x;
    const int i0 = b * EPB + t * IPT;
    const int lane = t & 31;
    const int wid  = t >> 5;

    const int4* p = reinterpret_cast<const int4*>(ids + i0);
    int4 a0 = p[0], a1 = p[1], a2 = p[2], a3 = p[3];

    // predecessor value = neighbor thread's last element (a3.w)
    __shared__ int warp_last[BLK / 32];
    const int nprev = __shfl_up_sync(0xFFFFFFFFu, a3.w, 1);
    if (lane == 31) warp_last[wid] = a3.w;
    __syncthreads();
    int first_prev;
    if (t == 0)         first_prev = (b == 0) ? ~a0.x : ids[i0 - 1];
    else if (lane == 0) first_prev = warp_last[wid - 1];
    else                first_prev = nprev;

    // boundary bitmask
    unsigned bm = 0;
    bm |= (unsigned)(a0.x != first_prev) << 0;
    bm |= (unsigned)(a0.y != a0.x) << 1;
    bm |= (unsigned)(a0.z != a0.y) << 2;
    bm |= (unsigned)(a0.w != a0.z) << 3;
    bm |= (unsigned)(a1.x != a0.w) << 4;
    bm |= (unsigned)(a1.y != a1.x) << 5;
    bm |= (unsigned)(a1.z != a1.y) << 6;
    bm |= (unsigned)(a1.w != a1.z) << 7;
    bm |= (unsigned)(a2.x != a1.w) << 8;
    bm |= (unsigned)(a2.y != a2.x) << 9;
    bm |= (unsigned)(a2.z != a2.y) << 10;
    bm |= (unsigned)(a2.w != a2.z) << 11;
    bm |= (unsigned)(a3.x != a2.w) << 12;
    bm |= (unsigned)(a3.y != a3.x) << 13;
    bm |= (unsigned)(a3.z != a3.y) << 14;
    bm |= (unsigned)(a3.w != a3.z) << 15;
    const int cnt = __popc(bm);

    // block-wide exclusive scan of per-thread counts (2-level shuffle)
    int s = cnt;
#pragma unroll
    for (int off = 1; off < 32; off <<= 1) {
        int x = __shfl_up_sync(0xFFFFFFFFu, s, off);
        if (lane >= off) s += x;
    }
    __shared__ int ws[BLK / 32];
    if (lane == 31) ws[wid] = s;
    __syncthreads();
    if (wid == 0 && lane < BLK / 32) {
        int x = ws[lane];
        int y = x;
#pragma unroll
        for (int off = 1; off < BLK / 32; off <<= 1) {
            int z = __shfl_up_sync(0xFFu, y, off);
            if (lane >= off) y += z;
        }
        ws[lane] = y - x;                        // exclusive warp base
        if (lane == BLK / 32 - 1) g_block_cnt[b] = y;   // block total
    }
    __syncthreads();
    int r = ws[wid] + (s - cnt);                 // local rank within block

    // scatter ONLY set bits; ONE STG.64 per run. Value reloaded via ids[]
    // (line is L1-resident; avoids a dynamic register-array index).
    const int seg = b * EPB;
    while (bm) {
        const int j = __ffs(bm) - 1;
        bm &= bm - 1;
        g_stash[seg + r] = make_int2(i0 + j, ids[i0 + j]);
        r++;
    }
}

// ---------------------------------------------------------------------------
// Kernel C: block b computes base = sum(g_block_cnt[0..b-1]) directly (all
// counts final — previous kernel ended; <=4 hot-L2 loads per thread), then
// copies its stash segment to the final rank-indexed SoA arrays.
// ---------------------------------------------------------------------------
__global__ __launch_bounds__(BLK) void k_apply() {
    const int b = blockIdx.x;
    const int t = threadIdx.x;
    const int lane = t & 31;
    const int wid  = t >> 5;

    int part = 0;
    for (int j = t; j < b; j += BLK)             // <= 4 iterations
        part += g_block_cnt[j];
#pragma unroll
    for (int off = 16; off > 0; off >>= 1)
        part += __shfl_down_sync(0xFFFFFFFFu, part, off);
    __shared__ int rs[BLK / 32];
    __shared__ int sBase;
    if (lane == 0) rs[wid] = part;
    __syncthreads();
    if (t == 0) {
        int acc = 0;
#pragma unroll
        for (int k = 0; k < BLK / 32; k++) acc += rs[k];
        sBase = acc;
    }
    __syncthreads();
    const int base = sBase;
    const int cnt  = g_block_cnt[b];

    if (b == NB - 1 && t == 0) g_num_runs = base + cnt;

    const int seg = b * EPB;
    for (int j = t; j < cnt; j += BLK) {
        const int2 e = g_stash[seg + j];
        g_start[base + j] = e.x;
        g_idf[base + j]   = (float)e.y;
    }
}

// ---------------------------------------------------------------------------
// Kernel 2: one WARP per EIGHT consecutive 128-float output windows.
// Flat layout (float32): out[0..M_CAP) = run_ids, then padded [M_CAP x 128].
// M_CAP % 128 == 1: window w>=2048 = col 127 of row A=w-2049 then cols
// 0..126 of row B=A+1 (window 2048: A=-1, head = run_ids[M_CAP-1] == -1).
// Per-window feats span is ONE contiguous 512B block [sB-off, sB-off+128),
// off = sB & 3: one aligned LDG.128 per lane + 0-2 warp shuffles keyed by
// the warp-uniform off. Lane-0 head (col 127 of row A) is one predicated
// scalar load. (R11/R12 proven version.)
// ---------------------------------------------------------------------------
__global__ __launch_bounds__(256) void k_fill(const float* __restrict__ feats,
                                              float* __restrict__ out) {
    if (blockIdx.x == 0 && threadIdx.x == 0)
        out[OUT_TOTAL - 1] = 0.0f;                // tail float (padding)

    const int W    = blockIdx.x * 8 + (threadIdx.x >> 5);   // warp-group id
    const int lane = threadIdx.x & 31;
    if (W >= NWG) return;
    const int w0  = W * WPW;
    const int nr1 = g_num_runs - 1;               // runs actually emitted

    if (W < 256) {
        // ---- run_ids region: 8 vectorized copies with tail masking ----
#pragma unroll
        for (int k = 0; k < WPW; k++) {
            float4 r = reinterpret_cast<const float4*>(g_idf)[(w0 + k) * 32 + lane];
            const int e = (w0 + k) * 128 + lane * 4;
            r.x = (e     < nr1) ? r.x : -1.0f;
            r.y = (e + 1 < nr1) ? r.y : -1.0f;
            r.z = (e + 2 < nr1) ? r.z : -1.0f;
            r.w = (e + 3 < nr1) ? r.w : -1.0f;
            __stcs(reinterpret_cast<float4*>(out) + (size_t)(w0 + k) * 32 + lane, r);
        }
        return;
    }

    // ---- padded region ----
    const int A0 = w0 - 2049;                     // head row of window 0

    // one coalesced metadata load: g_start[A0 .. A0+9]
    int mv = 0;
    if (lane < WPW + 2) {
        int idx = A0 + lane;
        idx = idx < 0 ? 0 : idx;
        idx = idx > nr1 ? nr1 : idx;              // clamp into written region
        mv = g_start[idx];
    }
    int m[WPW + 2];
#pragma unroll
    for (int j = 0; j < WPW + 2; j++) m[j] = __shfl_sync(0xFFFFFFFFu, mv, j);

    const bool l0 = (lane == 0);
    const int  c0 = 4 * lane - 1;                 // col of element 0

#pragma unroll
    for (int h = 0; h < 2; h++) {
        float4 V[4];
        float  head[4];
        int    offk[4];
        bool   okk[4], vBk[4];
        int    lenBk[4];

        // --- batched loads for 4 windows (MLP) ---
#pragma unroll
        for (int k2 = 0; k2 < 4; k2++) {
            const int k  = h * 4 + k2;
            const int w  = w0 + k;
            okk[k2] = (w < NW);
            const int A    = A0 + k;
            const int sA   = m[k];
            const int sB   = m[k + 1];
            const int sC   = m[k + 2];
            const bool vA  = ((unsigned)A       < (unsigned)nr1);
            vBk[k2]        = ((unsigned)(A + 1) < (unsigned)nr1);
            const int lenA = sB - sA;
            lenBk[k2]      = sC - sB;
            offk[k2]       = sB & 3;

            int q = (sB >> 2) + lane;
            q = q < N4 - 1 ? q : N4 - 1;
            V[k2] = make_float4(0.f, 0.f, 0.f, 0.f);
            if (okk[k2] && vBk[k2])
                V[k2] = __ldcs(reinterpret_cast<const float4*>(feats) + q);

            head[k2] = (A < 0) ? -1.0f : 0.0f;
            if (okk[k2] && l0 && vA && lenA > 127)
                head[k2] = __ldcs(feats + sA + 127);
        }

        // --- realign + mask + store per window ---
#pragma unroll
        for (int k2 = 0; k2 < 4; k2++) {
            const int off  = offk[k2];
            const int lenB = lenBk[k2];
            const bool vB  = vBk[k2];
            float e0, e1, e2, e3;

            if (off == 1) {
                e0 = V[k2].x; e1 = V[k2].y; e2 = V[k2].z; e3 = V[k2].w;
            } else if (off == 0) {
                const float pw = __shfl_up_sync(0xFFFFFFFFu, V[k2].w, 1);
                e0 = pw;      e1 = V[k2].x; e2 = V[k2].y; e3 = V[k2].z;
            } else if (off == 2) {
                const float nx = __shfl_down_sync(0xFFFFFFFFu, V[k2].x, 1);
                e0 = V[k2].y; e1 = V[k2].z; e2 = V[k2].w; e3 = nx;
            } else {
                const float nx = __shfl_down_sync(0xFFFFFFFFu, V[k2].x, 1);
                const float ny = __shfl_down_sync(0xFFFFFFFFu, V[k2].y, 1);
                e0 = V[k2].z; e1 = V[k2].w; e2 = nx;      e3 = ny;
            }

            e0 = (vB && c0     >= 0 && c0     < lenB) ? e0 : 0.0f;
            e1 = (vB && c0 + 1 < lenB) ? e1 : 0.0f;
            e2 = (vB && c0 + 2 < lenB) ? e2 : 0.0f;
            e3 = (vB && c0 + 3 < lenB) ? e3 : 0.0f;
            if (l0) e0 = head[k2];

            if (okk[k2])
                __stcs(reinterpret_cast<float4*>(out) +
                           (size_t)(w0 + h * 4 + k2) * 32 + lane,
                       make_float4(e0, e1, e2, e3));
        }
    }
}

// ---------------------------------------------------------------------------
extern "C" void kernel_launch(void* const* d_in, const int* in_sizes, int n_in,
                              void* d_out, int out_size) {
    const int*   ids   = (const int*)d_in[0];
    const float* feats = (const float*)d_in[1];
    float*       out   = (float*)d_out;

    k_count_stash<<<NB, BLK>>>(ids);
    k_apply<<<NB, BLK>>>();

    const int fill_blocks = (NWG + 7) / 8;        // 8 warp-groups per block
    k_fill<<<fill_blocks, 256>>>(feats, out);
}

// round 15
// speedup vs baseline: 1.1160x; 1.0580x over previous
#include <cuda_runtime.h>
#include <stdint.h>

// Problem constants (match reference)
#define N_ELEMS   4194304        // total elements
#define N4        (N_ELEMS / 4)  // feats as float4
#define NUM_IDS   262144
#define M_CAP     (NUM_IDS + 1)  // 262145 output rows
#define L_CAP     128
#define OUT_TOTAL (M_CAP + M_CAP * L_CAP)   // 33,816,705 floats
#define NW        264193         // full 128-float windows (NW*128 = OUT_TOTAL-1)
#define WPW       8              // windows per warp
#define NWG       33025          // warp-groups = ceil(NW / WPW)

// Scan decomposition: 1024 blocks * 4096 elems; 256 threads * 16 items/thread
#define NB        1024
#define EPB       4096
#define BLK       256
#define IPT       16

// Scratch (device globals: no allocation allowed)
__device__ __align__(16) int   g_start[M_CAP];     // start index of run s
__device__ __align__(16) float g_idf[M_CAP];       // float(id) for written runs
__device__ __align__(16) int2  g_stash[NB * EPB];  // per-block stash {start, id}
__device__ int g_block_cnt[NB];                    // runs per block
__device__ int g_num_runs;

// ---------------------------------------------------------------------------
// Kernel A: single ids read (4x LDG.128/thread); predecessor via shuffle/smem;
// boundary BITMASK (popc count, ffs scatter, ONE STG.64 per run); block-local
// rank scan; stash into the block's private segment. (R14 proven version.)
// ---------------------------------------------------------------------------
__global__ __launch_bounds__(BLK, 8) void k_count_stash(const int* __restrict__ ids) {
    const int b  = blockIdx.x;
    const int t  = threadIdx.x;
    const int i0 = b * EPB + t * IPT;
    const int lane = t & 31;
    const int wid  = t >> 5;

    const int4* p = reinterpret_cast<const int4*>(ids + i0);
    int4 a0 = p[0], a1 = p[1], a2 = p[2], a3 = p[3];

    // predecessor value = neighbor thread's last element (a3.w)
    __shared__ int warp_last[BLK / 32];
    const int nprev = __shfl_up_sync(0xFFFFFFFFu, a3.w, 1);
    if (lane == 31) warp_last[wid] = a3.w;
    __syncthreads();
    int first_prev;
    if (t == 0)         first_prev = (b == 0) ? ~a0.x : ids[i0 - 1];
    else if (lane == 0) first_prev = warp_last[wid - 1];
    else                first_prev = nprev;

    // boundary bitmask
    unsigned bm = 0;
    bm |= (unsigned)(a0.x != first_prev) << 0;
    bm |= (unsigned)(a0.y != a0.x) << 1;
    bm |= (unsigned)(a0.z != a0.y) << 2;
    bm |= (unsigned)(a0.w != a0.z) << 3;
    bm |= (unsigned)(a1.x != a0.w) << 4;
    bm |= (unsigned)(a1.y != a1.x) << 5;
    bm |= (unsigned)(a1.z != a1.y) << 6;
    bm |= (unsigned)(a1.w != a1.z) << 7;
    bm |= (unsigned)(a2.x != a1.w) << 8;
    bm |= (unsigned)(a2.y != a2.x) << 9;
    bm |= (unsigned)(a2.z != a2.y) << 10;
    bm |= (unsigned)(a2.w != a2.z) << 11;
    bm |= (unsigned)(a3.x != a2.w) << 12;
    bm |= (unsigned)(a3.y != a3.x) << 13;
    bm |= (unsigned)(a3.z != a3.y) << 14;
    bm |= (unsigned)(a3.w != a3.z) << 15;
    const int cnt = __popc(bm);

    // block-wide exclusive scan of per-thread counts (2-level shuffle)
    int s = cnt;
#pragma unroll
    for (int off = 1; off < 32; off <<= 1) {
        int x = __shfl_up_sync(0xFFFFFFFFu, s, off);
        if (lane >= off) s += x;
    }
    __shared__ int ws[BLK / 32];
    if (lane == 31) ws[wid] = s;
    __syncthreads();
    if (wid == 0 && lane < BLK / 32) {
        int x = ws[lane];
        int y = x;
#pragma unroll
        for (int off = 1; off < BLK / 32; off <<= 1) {
            int z = __shfl_up_sync(0xFFu, y, off);
            if (lane >= off) y += z;
        }
        ws[lane] = y - x;                        // exclusive warp base
        if (lane == BLK / 32 - 1) g_block_cnt[b] = y;   // block total
    }
    __syncthreads();
    int r = ws[wid] + (s - cnt);                 // local rank within block

    const int seg = b * EPB;
    while (bm) {
        const int j = __ffs(bm) - 1;
        bm &= bm - 1;
        g_stash[seg + r] = make_int2(i0 + j, ids[i0 + j]);
        r++;
    }
}

// ---------------------------------------------------------------------------
// Kernel C (PDL secondary): waits for k_count_stash via grid-dep-sync, then
// block b sums g_block_cnt[0..b-1] directly and copies its stash segment to
// the final rank-indexed SoA arrays.
// ---------------------------------------------------------------------------
__global__ __launch_bounds__(BLK) void k_apply() {
    const int b = blockIdx.x;
    const int t = threadIdx.x;
    const int lane = t & 31;
    const int wid  = t >> 5;

    cudaGridDependencySynchronize();             // upstream data now visible

    int part = 0;
    for (int j = t; j < b; j += BLK)             // <= 4 iterations
        part += g_block_cnt[j];
#pragma unroll
    for (int off = 16; off > 0; off >>= 1)
        part += __shfl_down_sync(0xFFFFFFFFu, part, off);
    __shared__ int rs[BLK / 32];
    __shared__ int sBase;
    if (lane == 0) rs[wid] = part;
    __syncthreads();
    if (t == 0) {
        int acc = 0;
#pragma unroll
        for (int k = 0; k < BLK / 32; k++) acc += rs[k];
        sBase = acc;
    }
    __syncthreads();
    const int base = sBase;
    const int cnt  = g_block_cnt[b];

    if (b == NB - 1 && t == 0) g_num_runs = base + cnt;

    const int seg = b * EPB;
    for (int j = t; j < cnt; j += BLK) {
        const int2 e = g_stash[seg + j];
        g_start[base + j] = e.x;
        g_idf[base + j]   = (float)e.y;
    }
}

// ---------------------------------------------------------------------------
// Kernel 2 (PDL secondary): one WARP per EIGHT consecutive 128-float windows.
// Flat layout (float32): out[0..M_CAP) = run_ids, then padded [M_CAP x 128].
// M_CAP % 128 == 1: window w>=2048 = col 127 of row A=w-2049 then cols
// 0..126 of row B=A+1 (window 2048: A=-1, head = run_ids[M_CAP-1] == -1).
// Per-window feats span = ONE contiguous 512B block, one aligned LDG.128
// per lane + 0-2 shuffles keyed by warp-uniform off. (R11/R12 proven.)
// ---------------------------------------------------------------------------
__global__ __launch_bounds__(256) void k_fill(const float* __restrict__ feats,
                                              float* __restrict__ out) {
    const int W    = blockIdx.x * 8 + (threadIdx.x >> 5);   // warp-group id
    const int lane = threadIdx.x & 31;

    cudaGridDependencySynchronize();             // g_start/g_idf/g_num_runs ready

    if (blockIdx.x == 0 && threadIdx.x == 0)
        out[OUT_TOTAL - 1] = 0.0f;                // tail float (padding)
    if (W >= NWG) return;
    const int w0  = W * WPW;
    const int nr1 = g_num_runs - 1;               // runs actually emitted

    if (W < 256) {
        // ---- run_ids region: 8 vectorized copies with tail masking ----
#pragma unroll
        for (int k = 0; k < WPW; k++) {
            float4 r = reinterpret_cast<const float4*>(g_idf)[(w0 + k) * 32 + lane];
            const int e = (w0 + k) * 128 + lane * 4;
            r.x = (e     < nr1) ? r.x : -1.0f;
            r.y = (e + 1 < nr1) ? r.y : -1.0f;
            r.z = (e + 2 < nr1) ? r.z : -1.0f;
            r.w = (e + 3 < nr1) ? r.w : -1.0f;
            __stcs(reinterpret_cast<float4*>(out) + (size_t)(w0 + k) * 32 + lane, r);
        }
        return;
    }

    // ---- padded region ----
    const int A0 = w0 - 2049;                     // head row of window 0

    int mv = 0;
    if (lane < WPW + 2) {
        int idx = A0 + lane;
        idx = idx < 0 ? 0 : idx;
        idx = idx > nr1 ? nr1 : idx;              // clamp into written region
        mv = g_start[idx];
    }
    int m[WPW + 2];
#pragma unroll
    for (int j = 0; j < WPW + 2; j++) m[j] = __shfl_sync(0xFFFFFFFFu, mv, j);

    const bool l0 = (lane == 0);
    const int  c0 = 4 * lane - 1;                 // col of element 0

#pragma unroll
    for (int h = 0; h < 2; h++) {
        float4 V[4];
        float  head[4];
        int    offk[4];
        bool   okk[4], vBk[4];
        int    lenBk[4];

#pragma unroll
        for (int k2 = 0; k2 < 4; k2++) {
            const int k  = h * 4 + k2;
            const int w  = w0 + k;
            okk[k2] = (w < NW);
            const int A    = A0 + k;
            const int sA   = m[k];
            const int sB   = m[k + 1];
            const int sC   = m[k + 2];
            const bool vA  = ((unsigned)A       < (unsigned)nr1);
            vBk[k2]        = ((unsigned)(A + 1) < (unsigned)nr1);
            const int lenA = sB - sA;
            lenBk[k2]      = sC - sB;
            offk[k2]       = sB & 3;

            int q = (sB >> 2) + lane;
            q = q < N4 - 1 ? q : N4 - 1;
            V[k2] = make_float4(0.f, 0.f, 0.f, 0.f);
            if (okk[k2] && vBk[k2])
                V[k2] = __ldcs(reinterpret_cast<const float4*>(feats) + q);

            head[k2] = (A < 0) ? -1.0f : 0.0f;
            if (okk[k2] && l0 && vA && lenA > 127)
                head[k2] = __ldcs(feats + sA + 127);
        }

#pragma unroll
        for (int k2 = 0; k2 < 4; k2++) {
            const int off  = offk[k2];
            const int lenB = lenBk[k2];
            const bool vB  = vBk[k2];
            float e0, e1, e2, e3;

            if (off == 1) {
                e0 = V[k2].x; e1 = V[k2].y; e2 = V[k2].z; e3 = V[k2].w;
            } else if (off == 0) {
                const float pw = __shfl_up_sync(0xFFFFFFFFu, V[k2].w, 1);
                e0 = pw;      e1 = V[k2].x; e2 = V[k2].y; e3 = V[k2].z;
            } else if (off == 2) {
                const float nx = __shfl_down_sync(0xFFFFFFFFu, V[k2].x, 1);
                e0 = V[k2].y; e1 = V[k2].z; e2 = V[k2].w; e3 = nx;
            } else {
                const float nx = __shfl_down_sync(0xFFFFFFFFu, V[k2].x, 1);
                const float ny = __shfl_down_sync(0xFFFFFFFFu, V[k2].y, 1);
                e0 = V[k2].z; e1 = V[k2].w; e2 = nx;      e3 = ny;
            }

            e0 = (vB && c0     >= 0 && c0     < lenB) ? e0 : 0.0f;
            e1 = (vB && c0 + 1 < lenB) ? e1 : 0.0f;
            e2 = (vB && c0 + 2 < lenB) ? e2 : 0.0f;
            e3 = (vB && c0 + 3 < lenB) ? e3 : 0.0f;
            if (l0) e0 = head[k2];

            if (okk[k2])
                __stcs(reinterpret_cast<float4*>(out) +
                           (size_t)(w0 + h * 4 + k2) * 32 + lane,
                       make_float4(e0, e1, e2, e3));
        }
    }
}

// ---------------------------------------------------------------------------
extern "C" void kernel_launch(void* const* d_in, const int* in_sizes, int n_in,
                              void* d_out, int out_size) {
    const int*   ids   = (const int*)d_in[0];
    const float* feats = (const float*)d_in[1];
    float*       out   = (float*)d_out;

    k_count_stash<<<NB, BLK>>>(ids);

    // PDL: overlap the dependent kernels' launch/preamble with the upstream
    // kernel's execution; device-side cudaGridDependencySynchronize() gates
    // all upstream-data reads (no early trigger upstream -> full completion
    // + visibility semantics).
    cudaLaunchAttribute attr[1];
    attr[0].id = cudaLaunchAttributeProgrammaticStreamSerialization;
    attr[0].val.programmaticStreamSerializationAllowed = 1;

    {
        cudaLaunchConfig_t cfg = {};
        cfg.gridDim  = dim3(NB);
        cfg.blockDim = dim3(BLK);
        cfg.attrs    = attr;
        cfg.numAttrs = 1;
        cudaLaunchKernelEx(&cfg, k_apply);
    }
    {
        const int fill_blocks = (NWG + 7) / 8;    // 8 warp-groups per block
        cudaLaunchConfig_t cfg = {};
        cfg.gridDim  = dim3(fill_blocks);
        cfg.blockDim = dim3(256);
        cfg.attrs    = attr;
        cfg.numAttrs = 1;
        cudaLaunchKernelEx(&cfg, k_fill, feats, out);
    }
}